// round 9
// baseline (speedup 1.0000x reference)
#include <cuda_runtime.h>
#include <cuda_fp16.h>
#include <math.h>
#include <stdint.h>

typedef unsigned long long ull;

constexpr int kT  = 2048;
constexpr int kDm = 1024;
constexpr int kDi = 2048;
constexpr int kNL = 4;
constexpr int kNS = 16;
constexpr int kV  = 32000;
constexpr int kXP = 33;

// A operands: fp16 packed tiles, 128 rows x 32 halves (8KB), XOR-swizzled.
// B operands: split per 128-col tile: rows 0-63 -> fp16 swizzled 64x32 (4KB),
//             rows 64-127 -> fp32 k-major [32k][64n] (8KB).
__device__ float  g_x  [kT * kDm];
__device__ __align__(16) __half g_xnh[kT * kDm];
__device__ float  g_xz [kT * 2 * kDi];
__device__ float  g_u  [kT * kDi];
__device__ float  g_xp [kT * kXP];
__device__ __align__(16) __half g_ygh[kT * kDi];
// scan prep buffers
__device__ float g_dt [kT * kDi];
__device__ float g_dtu[kT * kDi];
__device__ float g_zs [kT * kDi];
__device__ float g_w2 [kT * kDi];
// packed weights
__device__ __align__(16) __half g_b16_in [kNL * 2048 * 1024];
__device__ __align__(16) float  g_b32_in [kNL * 2048 * 1024];
__device__ __align__(16) __half g_b16_out[kNL * 512 * 2048];
__device__ __align__(16) float  g_b32_out[kNL * 512 * 2048];
__device__ __align__(16) __half g_b16_emb[16000 * 1024];
__device__ __align__(16) float  g_b32_emb[16000 * 1024];

__device__ __forceinline__ uint32_t smem_u32(const void* p) {
    uint32_t a;
    asm("{ .reg .u64 t; cvta.to.shared.u64 t, %1; cvt.u32.u64 %0, t; }"
        : "=r"(a) : "l"(p));
    return a;
}
#define MBAR_INIT(a, n) \
    asm volatile("mbarrier.init.shared.b64 [%0], %1;" :: "r"(a), "r"(n) : "memory")
#define MBAR_EXPECT_TX(a, tx) \
    asm volatile("mbarrier.arrive.expect_tx.shared.b64 _, [%0], %1;" \
                 :: "r"(a), "r"(tx) : "memory")
#define MBAR_WAIT(a, ph) do {                                                \
    asm volatile(                                                            \
        "{\n\t.reg .pred P;\n"                                               \
        "W%=:\n\t"                                                           \
        "mbarrier.try_wait.parity.acquire.cta.shared::cta.b64 P, [%0], %1, 0x989680;\n\t" \
        "@P bra.uni D%=;\n\t"                                                \
        "bra.uni W%=;\n"                                                     \
        "D%=:\n\t}"                                                          \
        :: "r"(a), "r"(ph) : "memory");                                      \
} while (0)
#define BULK_LD(dst, src, bytes, bar) \
    asm volatile("cp.async.bulk.shared::cluster.global.mbarrier::complete_tx::bytes " \
                 "[%0], [%1], %2, [%3];" \
                 :: "r"(dst), "l"(src), "r"(bytes), "r"(bar) : "memory")
#define FFMA2(acc, a2, b2) \
    asm("fma.rn.f32x2 %0, %1, %2, %0;" : "+l"(acc) : "l"(a2), "l"(b2))

// ---------------------------------------------------------------------------
// B pack: fp16 half (rows 0-63 of each 128-row tile), swizzled
// ---------------------------------------------------------------------------
__global__ void pack_b16(const float* __restrict__ in,
                         __half* __restrict__ out, long NK, int K) {
    long i = (long)blockIdx.x * blockDim.x + threadIdx.x;
    long e = i * 4;
    if (e >= NK) return;
    int n = (int)(e / K), k = (int)(e % K);
    int rr = n & 127;
    if (rr >= 64) return;
    float4 v = *(const float4*)(in + e);
    int nb = n >> 7, kb = k >> 5, col = k & 31;
    size_t off = ((size_t)(nb * (K >> 5) + kb) * 4096) +
                 (uint32_t)((rr * 64 + col * 2) ^ ((rr & 7) << 3));
    __half2 h0 = __floats2half2_rn(v.x, v.y);
    __half2 h1 = __floats2half2_rn(v.z, v.w);
    uint2 u;
    u.x = *(uint32_t*)&h0; u.y = *(uint32_t*)&h1;
    *(uint2*)((char*)out + off) = u;
}

// ---------------------------------------------------------------------------
// B pack: fp32 half (rows 64-127), transposed to [32k][64n]. grid(N/128,K/32)
// ---------------------------------------------------------------------------
__global__ void pack_b32(const float* __restrict__ in,
                         float* __restrict__ out, int K) {
    __shared__ float smT[64][33];
    int nb = blockIdx.x, kb = blockIdx.y;
    const float* src = in + ((size_t)nb * 128 + 64) * K + kb * 32;
    for (int i = threadIdx.x; i < 2048; i += 256) {
        int r = i >> 5, k = i & 31;
        smT[r][k] = src[(size_t)r * K + k];
    }
    __syncthreads();
    float* dst = out + (size_t)(nb * (K >> 5) + kb) * 2048;
    for (int i = threadIdx.x; i < 2048; i += 256) {
        int k = i >> 6, r = i & 63;
        dst[i] = smT[r][k];
    }
}

__global__ void embed_kernel(const int* __restrict__ idx,
                             const float* __restrict__ emb) {
    int t = blockIdx.x;
    int row = idx[t];
    ((float4*)(g_x + (size_t)t * kDm))[threadIdx.x] =
        ((const float4*)(emb + (size_t)row * kDm))[threadIdx.x];
}

__global__ void rmsnorm_kernel(const float* __restrict__ in,
                               const float* __restrict__ w,
                               __half* __restrict__ out) {
    __shared__ float red[8];
    __shared__ float s_scale;
    int t = blockIdx.x;
    float4 v = ((const float4*)(in + (size_t)t * kDm))[threadIdx.x];
    float ss = v.x * v.x + v.y * v.y + v.z * v.z + v.w * v.w;
    #pragma unroll
    for (int o = 16; o; o >>= 1) ss += __shfl_xor_sync(0xffffffffu, ss, o);
    int warp = threadIdx.x >> 5, lane = threadIdx.x & 31;
    if (lane == 0) red[warp] = ss;
    __syncthreads();
    if (threadIdx.x == 0) {
        float s = 0.f;
        #pragma unroll
        for (int i = 0; i < 8; i++) s += red[i];
        s_scale = rsqrtf(s / (float)kDm + 1e-5f);
    }
    __syncthreads();
    float sc = s_scale;
    float4 wv = ((const float4*)w)[threadIdx.x];
    __half2 h0 = __floats2half2_rn(v.x * sc * wv.x, v.y * sc * wv.y);
    __half2 h1 = __floats2half2_rn(v.z * sc * wv.z, v.w * sc * wv.w);
    int d0 = threadIdx.x * 4;
    int tb = t >> 7, r = t & 127, kb = d0 >> 5, col = d0 & 31;
    size_t off = ((size_t)(tb * (kDm >> 5) + kb) * 8192) +
                 (uint32_t)((r * 64 + col * 2) ^ ((r & 7) << 3));
    uint2 u;
    u.x = *(uint32_t*)&h0; u.y = *(uint32_t*)&h1;
    *(uint2*)((char*)out + off) = u;
}

// ---------------------------------------------------------------------------
// Warp-split hybrid GEMM: C[M,N] = A @ B^T (+C).  128x128 tile, 256 threads.
// Warps 0-3: mma.sync fp16 on cols [0,64). Warps 4-7: FFMA2 fp32 on [64,128).
// Per stage buf: [A16 8KB][B16 4KB][B32 8KB] = 20480B, S=3.
// ---------------------------------------------------------------------------
constexpr int GD = 1024 + 3 * 20480;   // 62464

__global__ __launch_bounds__(256, 2)
void gemm_ws(const __half* __restrict__ Ah, const __half* __restrict__ B16,
             const float* __restrict__ B32, float* __restrict__ C,
             int M, int N, int K, int acc_flag) {
    extern __shared__ char sm[];
    uint32_t sb = smem_u32(sm);
    int tid = threadIdx.x, lane = tid & 31, wrp = tid >> 5;
    int NKt = K >> 5;
    const char* gA  = (const char*)Ah  + (size_t)blockIdx.y * NKt * 8192;
    const char* g16 = (const char*)B16 + (size_t)blockIdx.x * NKt * 4096;
    const char* g32 = (const char*)B32 + (size_t)blockIdx.x * NKt * 8192;

    if (tid == 0) {
        #pragma unroll
        for (int s = 0; s < 3; s++) MBAR_INIT(sb + 8 * s, 1);
    }
    __syncthreads();
    auto issue = [&](int j) {
        uint32_t bar = sb + 8 * (j % 3);
        uint32_t d   = sb + 1024 + (j % 3) * 20480;
        MBAR_EXPECT_TX(bar, 20480u);
        BULK_LD(d,         gA  + (size_t)j * 8192, 8192u, bar);
        BULK_LD(d + 8192,  g16 + (size_t)j * 4096, 4096u, bar);
        BULK_LD(d + 12288, g32 + (size_t)j * 8192, 8192u, bar);
    };
    if (tid == 0) { issue(0); issue(1); }

    if (wrp < 4) {
        // ----------- TENSOR: cols [0,64) -----------
        int wm = wrp >> 1, wn = wrp & 1;
        int l2 = lane & 3, l4 = lane >> 2;
        float acc[4][4][4];
        #pragma unroll
        for (int i = 0; i < 4; i++)
            #pragma unroll
            for (int j = 0; j < 4; j++)
                #pragma unroll
                for (int r = 0; r < 4; r++) acc[i][j][r] = 0.f;
        uint32_t cx[4];
        #pragma unroll
        for (int p = 0; p < 4; p++)
            cx[p] = (uint32_t)((p * 16 + 4 * l2) ^ (l4 << 3));

        for (int ks = 0; ks < NKt; ks++) {
            MBAR_WAIT(sb + 8 * (ks % 3), (ks / 3) & 1);
            const char* As = sm + 1024 + (ks % 3) * 20480;
            const char* Bs = As + 8192;
            #pragma unroll
            for (int ph = 0; ph < 2; ph++) {
                uint32_t af[4][4], bf[4][2];
                #pragma unroll
                for (int mi = 0; mi < 4; mi++) {
                    uint32_t rb = (uint32_t)(wm * 64 + mi * 16 + l4) * 64;
                    af[mi][0] = *(const uint32_t*)(As + rb       + cx[ph * 2]);
                    af[mi][1] = *(const uint32_t*)(As + rb + 512 + cx[ph * 2]);
                    af[mi][2] = *(const uint32_t*)(As + rb       + cx[ph * 2 + 1]);
                    af[mi][3] = *(const uint32_t*)(As + rb + 512 + cx[ph * 2 + 1]);
                }
                #pragma unroll
                for (int ni = 0; ni < 4; ni++) {
                    uint32_t rb = (uint32_t)(wn * 32 + ni * 8 + l4) * 64;
                    bf[ni][0] = *(const uint32_t*)(Bs + rb + cx[ph * 2]);
                    bf[ni][1] = *(const uint32_t*)(Bs + rb + cx[ph * 2 + 1]);
                }
                #pragma unroll
                for (int mi = 0; mi < 4; mi++)
                    #pragma unroll
                    for (int ni = 0; ni < 4; ni++) {
                        asm volatile(
                            "mma.sync.aligned.m16n8k16.row.col.f32.f16.f16.f32 "
                            "{%0,%1,%2,%3}, {%4,%5,%6,%7}, {%8,%9}, {%0,%1,%2,%3};"
                            : "+f"(acc[mi][ni][0]), "+f"(acc[mi][ni][1]),
                              "+f"(acc[mi][ni][2]), "+f"(acc[mi][ni][3])
                            : "r"(af[mi][0]), "r"(af[mi][1]),
                              "r"(af[mi][2]), "r"(af[mi][3]),
                              "r"(bf[ni][0]), "r"(bf[ni][1]));
                    }
            }
            __syncthreads();
            if (tid == 0 && ks + 2 < NKt) issue(ks + 2);
        }
        #pragma unroll
        for (int mi = 0; mi < 4; mi++) {
            int row0 = blockIdx.y * 128 + wm * 64 + mi * 16 + l4;
            #pragma unroll
            for (int ni = 0; ni < 4; ni++) {
                int col0 = blockIdx.x * 128 + wn * 32 + ni * 8 + 2 * l2;
                float2* p0 = (float2*)(C + (size_t)row0 * N + col0);
                float2* p1 = (float2*)(C + (size_t)(row0 + 8) * N + col0);
                if (acc_flag) {
                    float2 v0 = *p0, v1 = *p1;
                    v0.x += acc[mi][ni][0]; v0.y += acc[mi][ni][1];
                    v1.x += acc[mi][ni][2]; v1.y += acc[mi][ni][3];
                    *p0 = v0; *p1 = v1;
                } else {
                    *p0 = make_float2(acc[mi][ni][0], acc[mi][ni][1]);
                    *p1 = make_float2(acc[mi][ni][2], acc[mi][ni][3]);
                }
            }
        }
    } else {
        // ----------- SIMT f32x2: cols [64,128) -----------
        int s = wrp - 4;
        int g = lane >> 2, q = lane & 3;
        int rbase = (s >> 1) * 64;
        int creg  = (s & 1) * 32;
        ull acc2[8][4];
        #pragma unroll
        for (int i = 0; i < 8; i++)
            #pragma unroll
            for (int j = 0; j < 4; j++) acc2[i][j] = 0ull;

        for (int ks = 0; ks < NKt; ks++) {
            MBAR_WAIT(sb + 8 * (ks % 3), (ks / 3) & 1);
            const char* As = sm + 1024 + (ks % 3) * 20480;
            const float* Bs = (const float*)(As + 12288);
            #pragma unroll 2
            for (int kp = 0; kp < 16; kp++) {
                float2 a2[8];
                #pragma unroll
                for (int i = 0; i < 8; i++) {
                    uint32_t u = *(const uint32_t*)(
                        As + (uint32_t)(rbase + g + 8 * i) * 64 +
                        (uint32_t)((kp * 4) ^ (g << 3)));
                    a2[i] = __half22float2(*(const __half2*)&u);
                }
                #pragma unroll
                for (int hf = 0; hf < 2; hf++) {
                    int k = 2 * kp + hf;
                    ull bv[4];
                    #pragma unroll
                    for (int j = 0; j < 4; j++)
                        bv[j] = *(const ull*)(Bs + k * 64 + creg + q * 8 + 2 * j);
                    #pragma unroll
                    for (int i = 0; i < 8; i++) {
                        float a = hf ? a2[i].y : a2[i].x;
                        ull aa;
                        asm("mov.b64 %0, {%1, %1};" : "=l"(aa) : "f"(a));
                        FFMA2(acc2[i][0], aa, bv[0]);
                        FFMA2(acc2[i][1], aa, bv[1]);
                        FFMA2(acc2[i][2], aa, bv[2]);
                        FFMA2(acc2[i][3], aa, bv[3]);
                    }
                }
            }
            __syncthreads();
        }
        #pragma unroll
        for (int i = 0; i < 8; i++) {
            int row = blockIdx.y * 128 + rbase + g + 8 * i;
            float* crow = C + (size_t)row * N + blockIdx.x * 128 + 64 + creg + q * 8;
            #pragma unroll
            for (int j = 0; j < 4; j++) {
                float2 v = *(const float2*)&acc2[i][j];
                float2* p = (float2*)(crow + 2 * j);
                if (acc_flag) {
                    float2 o = *p;
                    o.x += v.x; o.y += v.y;
                    *p = o;
                } else {
                    *p = v;
                }
            }
        }
    }
}

__global__ void conv_silu_kernel(const float* __restrict__ cw,
                                 const float* __restrict__ cb) {
    int i = blockIdx.x * blockDim.x + threadIdx.x;
    int t = i / kDi, c = i - t * kDi;
    float w0 = cw[c * 4 + 0], w1 = cw[c * 4 + 1];
    float w2 = cw[c * 4 + 2], w3 = cw[c * 4 + 3];
    const int stride = 2 * kDi;
    float s = cb[c];
    if (t >= 3) s += w0 * g_xz[(size_t)(t - 3) * stride + c];
    if (t >= 2) s += w1 * g_xz[(size_t)(t - 2) * stride + c];
    if (t >= 1) s += w2 * g_xz[(size_t)(t - 1) * stride + c];
    s += w3 * g_xz[(size_t)t * stride + c];
    g_u[i] = s / (1.f + __expf(-s));
}

__global__ void xproj_kernel(const float* __restrict__ W) {
    int t = blockIdx.x;
    int warp = threadIdx.x >> 5, lane = threadIdx.x & 31;
    const float4* ur = (const float4*)(g_u + (size_t)t * kDi);
    for (int j = warp; j < kXP; j += 8) {
        const float4* wr = (const float4*)(W + (size_t)j * kDi);
        float s = 0.f;
        #pragma unroll 4
        for (int k = lane; k < kDi / 4; k += 32) {
            float4 a = ur[k], b = wr[k];
            s += a.x * b.x + a.y * b.y + a.z * b.z + a.w * b.w;
        }
        #pragma unroll
        for (int o = 16; o; o >>= 1) s += __shfl_xor_sync(0xffffffffu, s, o);
        if (lane == 0) g_xp[t * kXP + j] = s;
    }
}

// Precompute dt, dt*u, silu(z), u*Dp*silu(z)
__global__ void prep_kernel(const float* __restrict__ dtw_,
                            const float* __restrict__ dtb_,
                            const float* __restrict__ Dp_) {
    int i = blockIdx.x * blockDim.x + threadIdx.x;
    int t = i >> 11, d = i & 2047;
    float xv = fmaf(g_xp[t * kXP], dtw_[d], dtb_[d]);
    float sp = fmaxf(xv, 0.f) + __logf(1.f + __expf(-fabsf(xv)));
    float u = g_u[i];
    float z = g_xz[(size_t)t * (2 * kDi) + kDi + d];
    float zs = z / (1.f + __expf(-z));
    g_dt[i]  = sp;
    g_dtu[i] = sp * u;
    g_zs[i]  = zs;
    g_w2[i]  = u * Dp_[d] * zs;
}

__global__ void scan_kernel(const float* __restrict__ A_log) {
    int tid = threadIdx.x;
    int n = tid & 15;
    int g = tid >> 4;
    int d = blockIdx.x * 8 + g;
    float a = -expf(A_log[(size_t)d * kNS + n]);
    int kb = d >> 5, col = d & 31;
    float h = 0.f;
    for (int t = 0; t < kT; t++) {
        int idx = t * kDi + d;
        float dt  = __ldg(g_dt + idx);
        float dtu = __ldg(g_dtu + idx);
        const float* xpr = g_xp + (size_t)t * kXP;
        float Bn = xpr[1 + n];
        float Cn = xpr[17 + n];
        float dA = __expf(dt * a);
        h = fmaf(dA, h, dtu * Bn);
        float p = h * Cn;
        p += __shfl_xor_sync(0xffffffffu, p, 8);
        p += __shfl_xor_sync(0xffffffffu, p, 4);
        p += __shfl_xor_sync(0xffffffffu, p, 2);
        p += __shfl_xor_sync(0xffffffffu, p, 1);
        if (n == 0) {
            float y = fmaf(p, g_zs[idx], g_w2[idx]);
            int tb = t >> 7, r = t & 127;
            size_t off = ((size_t)(tb * (kDi >> 5) + kb) * 8192) +
                         (uint32_t)((r * 64 + col * 2) ^ ((r & 7) << 3));
            *(__half*)((char*)g_ygh + off) = __float2half_rn(y);
        }
    }
}

extern "C" void kernel_launch(void* const* d_in, const int* in_sizes, int n_in,
                              void* d_out, int out_size) {
    const int*   idx        = (const int*)  d_in[0];
    const float* emb        = (const float*)d_in[1];
    const float* norm_w     = (const float*)d_in[2];
    const float* in_proj_w  = (const float*)d_in[3];
    const float* conv_w     = (const float*)d_in[4];
    const float* conv_b     = (const float*)d_in[5];
    const float* x_proj_w   = (const float*)d_in[6];
    const float* dt_proj_w  = (const float*)d_in[7];
    const float* dt_proj_b  = (const float*)d_in[8];
    const float* A_log      = (const float*)d_in[9];
    const float* D_param    = (const float*)d_in[10];
    const float* out_proj_w = (const float*)d_in[11];
    const float* norm_f_w   = (const float*)d_in[12];
    float* out = (float*)d_out;

    float *x, *xz, *b32i, *b32o, *b32e;
    __half *xnh, *ygh, *b16i, *b16o, *b16e;
    cudaGetSymbolAddress((void**)&x,    g_x);
    cudaGetSymbolAddress((void**)&xnh,  g_xnh);
    cudaGetSymbolAddress((void**)&xz,   g_xz);
    cudaGetSymbolAddress((void**)&ygh,  g_ygh);
    cudaGetSymbolAddress((void**)&b16i, g_b16_in);
    cudaGetSymbolAddress((void**)&b32i, g_b32_in);
    cudaGetSymbolAddress((void**)&b16o, g_b16_out);
    cudaGetSymbolAddress((void**)&b32o, g_b32_out);
    cudaGetSymbolAddress((void**)&b16e, g_b16_emb);
    cudaGetSymbolAddress((void**)&b32e, g_b32_emb);

    cudaFuncSetAttribute(gemm_ws,
                         cudaFuncAttributeMaxDynamicSharedMemorySize, GD);

    // Pack weights (deterministic, every call)
    for (int l = 0; l < kNL; l++) {
        const float* wi = in_proj_w + (size_t)l * 2 * kDi * kDm;
        const float* wo = out_proj_w + (size_t)l * kDm * kDi;
        long nki = (long)2 * kDi * kDm;
        long nko = (long)kDm * kDi;
        pack_b16<<<(int)((nki / 4 + 255) / 256), 256>>>(
            wi, b16i + (size_t)l * 2048 * 1024, nki, kDm);
        pack_b32<<<dim3(2 * kDi / 128, kDm / 32), 256>>>(
            wi, b32i + (size_t)l * 2048 * 1024, kDm);
        pack_b16<<<(int)((nko / 4 + 255) / 256), 256>>>(
            wo, b16o + (size_t)l * 512 * 2048, nko, kDi);
        pack_b32<<<dim3(kDm / 128, kDi / 32), 256>>>(
            wo, b32o + (size_t)l * 512 * 2048, kDi);
    }
    {
        long nke = (long)kV * kDm;
        pack_b16<<<(int)((nke / 4 + 255) / 256), 256>>>(emb, b16e, nke, kDm);
        pack_b32<<<dim3(kV / 128, kDm / 32), 256>>>(emb, b32e, kDm);
    }

    embed_kernel<<<kT, 256>>>(idx, emb);

    for (int l = 0; l < kNL; l++) {
        rmsnorm_kernel<<<kT, 256>>>(x, norm_w + (size_t)l * kDm, xnh);
        gemm_ws<<<dim3(2 * kDi / 128, kT / 128), 256, GD>>>(
            xnh, b16i + (size_t)l * 2048 * 1024, b32i + (size_t)l * 2048 * 1024,
            xz, kT, 2 * kDi, kDm, 0);
        conv_silu_kernel<<<kT * kDi / 256, 256>>>(
            conv_w + (size_t)l * kDi * 4, conv_b + (size_t)l * kDi);
        xproj_kernel<<<kT, 256>>>(x_proj_w + (size_t)l * kXP * kDi);
        prep_kernel<<<kT * kDi / 256, 256>>>(
            dt_proj_w + (size_t)l * kDi,
            dt_proj_b + (size_t)l * kDi,
            D_param + (size_t)l * kDi);
        scan_kernel<<<kDi / 8, 128>>>(A_log + (size_t)l * kDi * kNS);
        gemm_ws<<<dim3(kDm / 128, kT / 128), 256, GD>>>(
            ygh, b16o + (size_t)l * 512 * 2048, b32o + (size_t)l * 512 * 2048,
            x, kT, kDm, kDi, 1);
    }

    rmsnorm_kernel<<<kT, 256>>>(x, norm_f_w, xnh);
    gemm_ws<<<dim3(kV / 128, kT / 128), 256, GD>>>(
        xnh, b16e, b32e, out, kT, kV, kDm, 0);
}

// round 11
// speedup vs baseline: 1.5233x; 1.5233x over previous
#include <cuda_runtime.h>
#include <cuda_fp16.h>
#include <math.h>
#include <stdint.h>

constexpr int kT  = 2048;
constexpr int kDm = 1024;
constexpr int kDi = 2048;
constexpr int kNL = 4;
constexpr int kNS = 16;
constexpr int kV  = 32000;
constexpr int kXP = 33;

// Packed fp16 buffers. A tiles: 128 rows x 32 halves (8KB), XOR-swizzled.
// B tiles: R rows x 32 halves (R*64 bytes), R=256 for BN=256 GEMMs, 128 else.
__device__ float  g_x  [kT * kDm];
__device__ __align__(16) __half g_xnh[kT * kDm];
__device__ float  g_xz [kT * 2 * kDi];
__device__ float  g_u  [kT * kDi];
__device__ float  g_xp [kT * kXP];
__device__ __align__(16) __half g_ygh[kT * kDi];
__device__ __align__(16) __half g_wh_in [kNL * 2 * kDi * kDm];
__device__ __align__(16) __half g_wh_out[kNL * kDm * kDi];
__device__ __align__(16) __half g_embh  [kV * kDm];

__device__ __forceinline__ uint32_t smem_u32(const void* p) {
    uint32_t a;
    asm("{ .reg .u64 t; cvta.to.shared.u64 t, %1; cvt.u32.u64 %0, t; }"
        : "=r"(a) : "l"(p));
    return a;
}
#define MBAR_INIT(a, n) \
    asm volatile("mbarrier.init.shared.b64 [%0], %1;" :: "r"(a), "r"(n) : "memory")
#define MBAR_EXPECT_TX(a, tx) \
    asm volatile("mbarrier.arrive.expect_tx.shared.b64 _, [%0], %1;" \
                 :: "r"(a), "r"(tx) : "memory")
#define MBAR_WAIT(a, ph) do {                                                \
    asm volatile(                                                            \
        "{\n\t.reg .pred P;\n"                                               \
        "W%=:\n\t"                                                           \
        "mbarrier.try_wait.parity.acquire.cta.shared::cta.b64 P, [%0], %1, 0x989680;\n\t" \
        "@P bra.uni D%=;\n\t"                                                \
        "bra.uni W%=;\n"                                                     \
        "D%=:\n\t}"                                                          \
        :: "r"(a), "r"(ph) : "memory");                                      \
} while (0)
#define BULK_LD(dst, src, bytes, bar) \
    asm volatile("cp.async.bulk.shared::cluster.global.mbarrier::complete_tx::bytes " \
                 "[%0], [%1], %2, [%3];" \
                 :: "r"(dst), "l"(src), "r"(bytes), "r"(bar) : "memory")

// ---------------------------------------------------------------------------
// Weight pack: f32 [N,K] row-major -> fp16 tiles [nb][kb][R x 32], swizzled.
// (templated R: must match the consuming GEMM's BN)
// ---------------------------------------------------------------------------
template <int R>
__global__ void pack_w_kernel(const float* __restrict__ in,
                              __half* __restrict__ out, int N, int K) {
    long i = (long)blockIdx.x * blockDim.x + threadIdx.x;
    long e = i * 4;
    if (e >= (long)N * K) return;
    int n = (int)(e / K), k = (int)(e % K);
    float4 v = *(const float4*)(in + e);
    int nb = n / R, rr = n % R, kb = k >> 5, col = k & 31;
    int NKt = K >> 5;
    size_t off = ((size_t)(nb * NKt + kb) * (R * 64)) +
                 (uint32_t)((rr * 64 + col * 2) ^ ((rr & 7) << 3));
    __half2 h0 = __floats2half2_rn(v.x, v.y);
    __half2 h1 = __floats2half2_rn(v.z, v.w);
    uint2 u;
    u.x = *(uint32_t*)&h0; u.y = *(uint32_t*)&h1;
    *(uint2*)((char*)out + off) = u;
}

__global__ void embed_kernel(const int* __restrict__ idx,
                             const float* __restrict__ emb) {
    int t = blockIdx.x;
    int row = idx[t];
    ((float4*)(g_x + (size_t)t * kDm))[threadIdx.x] =
        ((const float4*)(emb + (size_t)row * kDm))[threadIdx.x];
}

__global__ void rmsnorm_kernel(const float* __restrict__ in,
                               const float* __restrict__ w,
                               __half* __restrict__ out) {
    __shared__ float red[8];
    __shared__ float s_scale;
    int t = blockIdx.x;
    float4 v = ((const float4*)(in + (size_t)t * kDm))[threadIdx.x];
    float ss = v.x * v.x + v.y * v.y + v.z * v.z + v.w * v.w;
    #pragma unroll
    for (int o = 16; o; o >>= 1) ss += __shfl_xor_sync(0xffffffffu, ss, o);
    int warp = threadIdx.x >> 5, lane = threadIdx.x & 31;
    if (lane == 0) red[warp] = ss;
    __syncthreads();
    if (threadIdx.x == 0) {
        float s = 0.f;
        #pragma unroll
        for (int i = 0; i < 8; i++) s += red[i];
        s_scale = rsqrtf(s / (float)kDm + 1e-5f);
    }
    __syncthreads();
    float sc = s_scale;
    float4 wv = ((const float4*)w)[threadIdx.x];
    __half2 h0 = __floats2half2_rn(v.x * sc * wv.x, v.y * sc * wv.y);
    __half2 h1 = __floats2half2_rn(v.z * sc * wv.z, v.w * sc * wv.w);
    int d0 = threadIdx.x * 4;
    int tb = t >> 7, r = t & 127, kb = d0 >> 5, col = d0 & 31;
    size_t off = ((size_t)(tb * (kDm >> 5) + kb) * 8192) +
                 (uint32_t)((r * 64 + col * 2) ^ ((r & 7) << 3));
    uint2 u;
    u.x = *(uint32_t*)&h0; u.y = *(uint32_t*)&h1;
    *(uint2*)((char*)out + off) = u;
}

// ---------------------------------------------------------------------------
// fp16 mma.sync NT GEMM with cp.async.bulk pipeline (R6, best known).
// ---------------------------------------------------------------------------
template <int BN, int THREADS>
__global__ __launch_bounds__(THREADS, (BN == 128) ? 2 : 1)
void gemm_bulk(const __half* __restrict__ Ap, const __half* __restrict__ Bp,
               float* __restrict__ C, int M, int N, int K, int acc_flag) {
    constexpr int S  = 3;
    constexpr int SB = 8192 + BN * 64;
    constexpr int WNN = BN / 32;
    extern __shared__ char sm[];
    uint32_t sb = smem_u32(sm);

    int tid = threadIdx.x, lane = tid & 31, wrp = tid >> 5;
    int wm = wrp / WNN, wn = wrp % WNN;
    int l2 = lane & 3, l4 = lane >> 2;
    int NKt = K >> 5;

    const char* gA = (const char*)Ap + (size_t)blockIdx.y * NKt * 8192;
    const char* gB = (const char*)Bp + (size_t)blockIdx.x * NKt * (BN * 64);

    if (tid == 0) {
        #pragma unroll
        for (int s = 0; s < S; s++) MBAR_INIT(sb + 8 * s, 1);
    }
    __syncthreads();

    auto issue = [&](int j) {
        uint32_t bar = sb + 8 * (j % S);
        uint32_t dA  = sb + 1024 + (j % S) * SB;
        MBAR_EXPECT_TX(bar, (uint32_t)SB);
        BULK_LD(dA, gA + (size_t)j * 8192, 8192u, bar);
        BULK_LD(dA + 8192, gB + (size_t)j * (BN * 64), (uint32_t)(BN * 64), bar);
    };
    if (tid == 0) { issue(0); issue(1); }

    float acc[4][4][4];
    #pragma unroll
    for (int i = 0; i < 4; i++)
        #pragma unroll
        for (int j = 0; j < 4; j++)
            #pragma unroll
            for (int r = 0; r < 4; r++) acc[i][j][r] = 0.f;

    uint32_t cx[4];
    #pragma unroll
    for (int p = 0; p < 4; p++) cx[p] = (uint32_t)((p * 16 + 4 * l2) ^ (l4 << 3));

    for (int ks = 0; ks < NKt; ks++) {
        MBAR_WAIT(sb + 8 * (ks % S), (ks / S) & 1);

        const char* As = sm + 1024 + (ks % S) * SB;
        const char* Bs = As + 8192;
        #pragma unroll
        for (int ph = 0; ph < 2; ph++) {
            uint32_t af[4][4];
            uint32_t bf[4][2];
            #pragma unroll
            for (int mi = 0; mi < 4; mi++) {
                uint32_t rb = (uint32_t)(wm * 64 + mi * 16 + l4) * 64;
                af[mi][0] = *(const uint32_t*)(As + rb       + cx[ph * 2]);
                af[mi][1] = *(const uint32_t*)(As + rb + 512 + cx[ph * 2]);
                af[mi][2] = *(const uint32_t*)(As + rb       + cx[ph * 2 + 1]);
                af[mi][3] = *(const uint32_t*)(As + rb + 512 + cx[ph * 2 + 1]);
            }
            #pragma unroll
            for (int ni = 0; ni < 4; ni++) {
                uint32_t rb = (uint32_t)(wn * 32 + ni * 8 + l4) * 64;
                bf[ni][0] = *(const uint32_t*)(Bs + rb + cx[ph * 2]);
                bf[ni][1] = *(const uint32_t*)(Bs + rb + cx[ph * 2 + 1]);
            }
            #pragma unroll
            for (int mi = 0; mi < 4; mi++)
                #pragma unroll
                for (int ni = 0; ni < 4; ni++) {
                    asm volatile(
                        "mma.sync.aligned.m16n8k16.row.col.f32.f16.f16.f32 "
                        "{%0,%1,%2,%3}, {%4,%5,%6,%7}, {%8,%9}, {%0,%1,%2,%3};"
                        : "+f"(acc[mi][ni][0]), "+f"(acc[mi][ni][1]),
                          "+f"(acc[mi][ni][2]), "+f"(acc[mi][ni][3])
                        : "r"(af[mi][0]), "r"(af[mi][1]),
                          "r"(af[mi][2]), "r"(af[mi][3]),
                          "r"(bf[ni][0]), "r"(bf[ni][1]));
                }
        }
        __syncthreads();
        if (tid == 0 && ks + 2 < NKt) issue(ks + 2);
    }

    #pragma unroll
    for (int mi = 0; mi < 4; mi++) {
        int row0 = blockIdx.y * 128 + wm * 64 + mi * 16 + l4;
        #pragma unroll
        for (int ni = 0; ni < 4; ni++) {
            int col0 = blockIdx.x * BN + wn * 32 + ni * 8 + 2 * l2;
            float2* p0 = (float2*)(C + (size_t)row0 * N + col0);
            float2* p1 = (float2*)(C + (size_t)(row0 + 8) * N + col0);
            if (acc_flag) {
                float2 v0 = *p0, v1 = *p1;
                v0.x += acc[mi][ni][0]; v0.y += acc[mi][ni][1];
                v1.x += acc[mi][ni][2]; v1.y += acc[mi][ni][3];
                *p0 = v0; *p1 = v1;
            } else {
                *p0 = make_float2(acc[mi][ni][0], acc[mi][ni][1]);
                *p1 = make_float2(acc[mi][ni][2], acc[mi][ni][3]);
            }
        }
    }
}

constexpr int SMEM_BN256 = 1024 + 3 * (8192 + 256 * 64);
constexpr int SMEM_BN128 = 1024 + 3 * (8192 + 128 * 64);

// ---------------------------------------------------------------------------
// Causal depthwise conv (K=4) + bias + silu; rolling window, 8 t per thread.
// ---------------------------------------------------------------------------
__global__ void conv_silu8_kernel(const float* __restrict__ cw,
                                  const float* __restrict__ cb) {
    int c  = blockIdx.x * 256 + threadIdx.x;
    int t0 = blockIdx.y * 8;
    const int stride = 2 * kDi;
    float w0 = cw[c * 4 + 0], w1 = cw[c * 4 + 1];
    float w2 = cw[c * 4 + 2], w3 = cw[c * 4 + 3];
    float b  = cb[c];
    float x0 = (t0 >= 3) ? g_xz[(size_t)(t0 - 3) * stride + c] : 0.f;
    float x1 = (t0 >= 2) ? g_xz[(size_t)(t0 - 2) * stride + c] : 0.f;
    float x2 = (t0 >= 1) ? g_xz[(size_t)(t0 - 1) * stride + c] : 0.f;
    #pragma unroll
    for (int i = 0; i < 8; i++) {
        float cur = g_xz[(size_t)(t0 + i) * stride + c];
        float s = b + w0 * x0 + w1 * x1 + w2 * x2 + w3 * cur;
        g_u[(size_t)(t0 + i) * kDi + c] = s / (1.f + __expf(-s));
        x0 = x1; x1 = x2; x2 = cur;
    }
}

// ---------------------------------------------------------------------------
// x_proj, 8 tokens per block: u rows staged in smem, W streamed once/block.
// ---------------------------------------------------------------------------
constexpr int XP_SMEM = 8 * kDi * 4;   // 65536

__global__ __launch_bounds__(256)
void xproj8_kernel(const float* __restrict__ W) {
    extern __shared__ float su[];      // [8][2048]
    int t0 = blockIdx.x * 8;
    const float4* usrc = (const float4*)(g_u + (size_t)t0 * kDi);
    for (int i = threadIdx.x; i < 8 * kDi / 4; i += 256)
        ((float4*)su)[i] = usrc[i];
    __syncthreads();

    int warp = threadIdx.x >> 5, lane = threadIdx.x & 31;
    for (int j = warp; j < kXP; j += 8) {
        const float4* wr = (const float4*)(W + (size_t)j * kDi);
        float acc[8];
        #pragma unroll
        for (int r = 0; r < 8; r++) acc[r] = 0.f;
        #pragma unroll 4
        for (int k = lane; k < kDi / 4; k += 32) {
            float4 bv = wr[k];
            #pragma unroll
            for (int r = 0; r < 8; r++) {
                float4 a = ((const float4*)(su + r * kDi))[k];
                acc[r] += a.x * bv.x + a.y * bv.y + a.z * bv.z + a.w * bv.w;
            }
        }
        #pragma unroll
        for (int r = 0; r < 8; r++) {
            float s = acc[r];
            #pragma unroll
            for (int o = 16; o; o >>= 1) s += __shfl_xor_sync(0xffffffffu, s, o);
            if (lane == 0) g_xp[(t0 + r) * kXP + j] = s;
        }
    }
}

// ---------------------------------------------------------------------------
// Selective scan -> packed swizzled fp16 (R6)
// ---------------------------------------------------------------------------
__global__ void scan_kernel(const float* __restrict__ A_log,
                            const float* __restrict__ dtw_,
                            const float* __restrict__ dtb_,
                            const float* __restrict__ Dp_) {
    int tid = threadIdx.x;
    int n = tid & 15;
    int g = tid >> 4;
    int d = blockIdx.x * 8 + g;
    float a   = -expf(A_log[(size_t)d * kNS + n]);
    float dtw = dtw_[d];
    float dtb = dtb_[d];
    float Dp  = Dp_[d];
    int kb = d >> 5, col = d & 31;
    float h = 0.f;
    for (int t = 0; t < kT; t++) {
        const float* xpr = g_xp + (size_t)t * kXP;
        float xv = xpr[0] * dtw + dtb;
        float dt = (xv > 20.f) ? xv : log1pf(__expf(xv));
        float Bn = xpr[1 + n];
        float Cn = xpr[17 + n];
        float ut = g_u[(size_t)t * kDi + d];
        float dA = __expf(dt * a);
        h = dA * h + (dt * ut) * Bn;
        float p = h * Cn;
        p += __shfl_xor_sync(0xffffffffu, p, 8);
        p += __shfl_xor_sync(0xffffffffu, p, 4);
        p += __shfl_xor_sync(0xffffffffu, p, 2);
        p += __shfl_xor_sync(0xffffffffu, p, 1);
        if (n == 0) {
            float z = g_xz[(size_t)t * (2 * kDi) + kDi + d];
            float y = p + ut * Dp;
            int tb = t >> 7, r = t & 127;
            size_t off = ((size_t)(tb * (kDi >> 5) + kb) * 8192) +
                         (uint32_t)((r * 64 + col * 2) ^ ((r & 7) << 3));
            *(__half*)((char*)g_ygh + off) =
                __float2half_rn(y * (z / (1.f + __expf(-z))));
        }
    }
}

// ---------------------------------------------------------------------------
extern "C" void kernel_launch(void* const* d_in, const int* in_sizes, int n_in,
                              void* d_out, int out_size) {
    const int*   idx        = (const int*)  d_in[0];
    const float* emb        = (const float*)d_in[1];
    const float* norm_w     = (const float*)d_in[2];
    const float* in_proj_w  = (const float*)d_in[3];
    const float* conv_w     = (const float*)d_in[4];
    const float* conv_b     = (const float*)d_in[5];
    const float* x_proj_w   = (const float*)d_in[6];
    const float* dt_proj_w  = (const float*)d_in[7];
    const float* dt_proj_b  = (const float*)d_in[8];
    const float* A_log      = (const float*)d_in[9];
    const float* D_param    = (const float*)d_in[10];
    const float* out_proj_w = (const float*)d_in[11];
    const float* norm_f_w   = (const float*)d_in[12];
    float* out = (float*)d_out;

    float *x, *xz;
    __half *xnh, *ygh, *wh_in, *wh_out, *embh;
    cudaGetSymbolAddress((void**)&x,      g_x);
    cudaGetSymbolAddress((void**)&xnh,    g_xnh);
    cudaGetSymbolAddress((void**)&xz,     g_xz);
    cudaGetSymbolAddress((void**)&ygh,    g_ygh);
    cudaGetSymbolAddress((void**)&wh_in,  g_wh_in);
    cudaGetSymbolAddress((void**)&wh_out, g_wh_out);
    cudaGetSymbolAddress((void**)&embh,   g_embh);

    cudaFuncSetAttribute(gemm_bulk<256, 512>,
                         cudaFuncAttributeMaxDynamicSharedMemorySize, SMEM_BN256);
    cudaFuncSetAttribute(gemm_bulk<128, 256>,
                         cudaFuncAttributeMaxDynamicSharedMemorySize, SMEM_BN128);
    cudaFuncSetAttribute(xproj8_kernel,
                         cudaFuncAttributeMaxDynamicSharedMemorySize, XP_SMEM);

    // Pack weights — tile row-count MUST match the consuming GEMM's BN.
    {
        long n1 = (long)kNL * 2 * kDi * kDm / 4;
        long n2 = (long)kNL * kDm * kDi / 4;
        long n3 = (long)kV * kDm / 4;
        pack_w_kernel<256><<<(int)((n1 + 255) / 256), 256>>>(in_proj_w,  wh_in,
                                                             kNL * 2 * kDi, kDm);
        pack_w_kernel<128><<<(int)((n2 + 255) / 256), 256>>>(out_proj_w, wh_out,
                                                             kNL * kDm, kDi);
        pack_w_kernel<256><<<(int)((n3 + 255) / 256), 256>>>(emb,        embh,
                                                             kV, kDm);
    }

    embed_kernel<<<kT, 256>>>(idx, emb);

    for (int l = 0; l < kNL; l++) {
        rmsnorm_kernel<<<kT, 256>>>(x, norm_w + (size_t)l * kDm, xnh);
        gemm_bulk<256, 512><<<dim3(2 * kDi / 256, kT / 128), 512, SMEM_BN256>>>(
            xnh, wh_in + (size_t)l * 2 * kDi * kDm, xz, kT, 2 * kDi, kDm, 0);
        conv_silu8_kernel<<<dim3(kDi / 256, kT / 8), 256>>>(
            conv_w + (size_t)l * kDi * 4, conv_b + (size_t)l * kDi);
        xproj8_kernel<<<kT / 8, 256, XP_SMEM>>>(x_proj_w + (size_t)l * kXP * kDi);
        scan_kernel<<<kDi / 8, 128>>>(
            A_log + (size_t)l * kDi * kNS,
            dt_proj_w + (size_t)l * kDi,
            dt_proj_b + (size_t)l * kDi,
            D_param + (size_t)l * kDi);
        gemm_bulk<128, 256><<<dim3(kDm / 128, kT / 128), 256, SMEM_BN128>>>(
            ygh, wh_out + (size_t)l * kDm * kDi, x, kT, kDm, kDi, 1);
    }

    rmsnorm_kernel<<<kT, 256>>>(x, norm_f_w, xnh);
    gemm_bulk<256, 512><<<dim3(kV / 256, kT / 128), 512, SMEM_BN256>>>(
        xnh, embh, out, kT, kV, kDm, 0);
}